// round 1
// baseline (speedup 1.0000x reference)
#include <cuda_runtime.h>
#include <cuda_bf16.h>

// ---------------- problem constants ----------------
#define BATCH   8
#define SEQ     2048
#define BS_TOT  (BATCH*SEQ)      // 16384 rows
#define DM      256              // d_model
#define DI      512              // d_inner
#define DST     16               // d_state
#define DTR     16               // dt_rank
#define NLAYER  4
#define DBC_W   48               // dt_rank + 2*d_state
#define NCHUNK  16
#define CHUNK   128              // SEQ / NCHUNK

// ---------------- scratch (device globals; no allocation allowed) ----------------
__device__ float g_h    [BS_TOT*DM];      // residual stream
__device__ float g_xn   [BS_TOT*DM];      // rmsnorm output
__device__ float g_xz   [BS_TOT*2*DI];    // in_proj output (u_pre | z)
__device__ float g_u    [BS_TOT*DI];      // conv+silu output
__device__ float g_dbc  [BS_TOT*DBC_W];   // x_proj output (dt | B | C)
__device__ float g_delta[BS_TOT*DI];      // softplus(dt)
__device__ float g_ya   [BS_TOT*DI];      // scan output * silu(z)
__device__ float g_ap   [BATCH*NCHUNK*DI*DST];  // chunk diag products
__device__ float g_hl   [BATCH*NCHUNK*DI*DST];  // chunk local final states
__device__ float g_hi   [BATCH*NCHUNK*DI*DST];  // chunk initial states

// ---------------- kernels ----------------

// h[r,d] = x[r,0]*w_in[d,0] + x[r,1]*w_in[d,1] + b_in[d]
__global__ void k_embed(const float* __restrict__ x, const float* __restrict__ w_in,
                        const float* __restrict__ b_in, float* __restrict__ h) {
    int i = blockIdx.x*blockDim.x + threadIdx.x;
    if (i >= BS_TOT*DM) return;
    int r = i >> 8, d = i & (DM-1);
    h[i] = x[2*r]*w_in[2*d] + x[2*r+1]*w_in[2*d+1] + b_in[d];
}

// RMSNorm: one block (256 threads) per row
__global__ void k_rmsnorm(const float* __restrict__ h, const float* __restrict__ w,
                          float* __restrict__ xn) {
    int r = blockIdx.x, d = threadIdx.x;
    float v = h[r*DM + d];
    float s = v*v;
    #pragma unroll
    for (int off = 16; off > 0; off >>= 1) s += __shfl_xor_sync(0xffffffffu, s, off);
    __shared__ float red[8];
    __shared__ float scale;
    int lane = d & 31, warp = d >> 5;
    if (lane == 0) red[warp] = s;
    __syncthreads();
    if (d == 0) {
        float t = 0.f;
        #pragma unroll
        for (int i = 0; i < 8; i++) t += red[i];
        scale = rsqrtf(t * (1.0f/DM) + 1e-5f);
    }
    __syncthreads();
    xn[r*DM + d] = v * scale * w[d];
}

// C[M,N] = A[M,K] @ B[N,K]^T  (both row-major, K contiguous). Optional accumulate.
// block: 256 threads, tile 128x64, thread tile 8x4, BK=16.
template<bool ACC>
__global__ __launch_bounds__(256)
void sgemm_nt(const float* __restrict__ A, const float* __restrict__ B,
              float* __restrict__ C, int K, int lda, int ldb, int ldc) {
    __shared__ float As[16][128];
    __shared__ float Bs[16][64];
    const int m0 = blockIdx.x * 128, n0 = blockIdx.y * 64;
    const int tid = threadIdx.x;
    const int tx = tid & 15, ty = tid >> 4;
    float acc[8][4];
    #pragma unroll
    for (int i = 0; i < 8; i++)
        #pragma unroll
        for (int j = 0; j < 4; j++) acc[i][j] = 0.f;

    for (int k0 = 0; k0 < K; k0 += 16) {
        #pragma unroll
        for (int j = 0; j < 2; j++) {
            int idx = tid + j*256;              // 0..511
            int m = idx >> 2, kq = idx & 3;
            float4 v = *(const float4*)(A + (m0+m)*lda + k0 + kq*4);
            As[kq*4+0][m] = v.x; As[kq*4+1][m] = v.y;
            As[kq*4+2][m] = v.z; As[kq*4+3][m] = v.w;
        }
        {
            int n = tid >> 2, kq = tid & 3;
            float4 v = *(const float4*)(B + (n0+n)*ldb + k0 + kq*4);
            Bs[kq*4+0][n] = v.x; Bs[kq*4+1][n] = v.y;
            Bs[kq*4+2][n] = v.z; Bs[kq*4+3][n] = v.w;
        }
        __syncthreads();
        #pragma unroll
        for (int kk = 0; kk < 16; kk++) {
            float4 b4 = *(const float4*)&Bs[kk][tx*4];
            float4 a0 = *(const float4*)&As[kk][ty*8];
            float4 a1 = *(const float4*)&As[kk][ty*8+4];
            float av[8] = {a0.x,a0.y,a0.z,a0.w,a1.x,a1.y,a1.z,a1.w};
            float bv[4] = {b4.x,b4.y,b4.z,b4.w};
            #pragma unroll
            for (int i = 0; i < 8; i++)
                #pragma unroll
                for (int j = 0; j < 4; j++)
                    acc[i][j] += av[i]*bv[j];
        }
        __syncthreads();
    }
    #pragma unroll
    for (int i = 0; i < 8; i++) {
        float* cp = C + (m0 + ty*8 + i)*ldc + n0 + tx*4;
        float4 v = make_float4(acc[i][0], acc[i][1], acc[i][2], acc[i][3]);
        if (ACC) {
            float4 o = *(const float4*)cp;
            v.x += o.x; v.y += o.y; v.z += o.z; v.w += o.w;
        }
        *(float4*)cp = v;
    }
}

__device__ __forceinline__ float silu(float x) { return x / (1.f + __expf(-x)); }

// causal depthwise conv (width 4) + bias + silu.  input: first DI cols of xz.
__global__ void k_conv(const float* __restrict__ xz, const float* __restrict__ cw,
                       const float* __restrict__ cb, float* __restrict__ u) {
    int i = blockIdx.x*blockDim.x + threadIdx.x;
    if (i >= BS_TOT*DI) return;
    int c = i & (DI-1), r = i >> 9, s = r & (SEQ-1);
    float4 w = *(const float4*)(cw + c*4);
    float acc = cb[c];
    if (s >= 3) acc += w.x * xz[(r-3)*2*DI + c];
    if (s >= 2) acc += w.y * xz[(r-2)*2*DI + c];
    if (s >= 1) acc += w.z * xz[(r-1)*2*DI + c];
    acc += w.w * xz[r*2*DI + c];
    u[i] = silu(acc);
}

// dbc = u @ x_proj_w^T : (16384 x 48), K=512. block (48,4), rows staged in smem.
__global__ void k_xproj(const float* __restrict__ u, const float* __restrict__ w,
                        float* __restrict__ dbc) {
    __shared__ float su[4*DI];
    int r0 = blockIdx.x * 4;
    int tid = threadIdx.y*48 + threadIdx.x;
    for (int i = tid; i < 4*DI; i += 192) su[i] = u[r0*DI + i];
    __syncthreads();
    int col = threadIdx.x, ry = threadIdx.y;
    const float4* w4 = (const float4*)(w + col*DI);
    const float4* u4 = (const float4*)(su + ry*DI);
    float acc = 0.f;
    #pragma unroll 8
    for (int k = 0; k < DI/4; k++) {
        float4 a = u4[k], b = __ldg(w4 + k);
        acc += a.x*b.x + a.y*b.y + a.z*b.z + a.w*b.w;
    }
    dbc[(r0+ry)*DBC_W + col] = acc;
}

// delta = softplus(dbc[:, :16] @ dt_proj_w^T + dt_proj_b)
__global__ void k_dt(const float* __restrict__ dbc, const float* __restrict__ dtw,
                     const float* __restrict__ dtb, float* __restrict__ delta) {
    int i = blockIdx.x*blockDim.x + threadIdx.x;
    if (i >= BS_TOT*DI) return;
    int c = i & (DI-1), r = i >> 9;
    const float4* d4 = (const float4*)(dbc + r*DBC_W);
    const float4* w4 = (const float4*)(dtw + c*DTR);
    float acc = dtb[c];
    #pragma unroll
    for (int q = 0; q < 4; q++) {
        float4 a = __ldg(d4 + q), b = __ldg(w4 + q);
        acc += a.x*b.x + a.y*b.y + a.z*b.z + a.w*b.w;
    }
    delta[i] = (acc > 20.f) ? acc : log1pf(__expf(acc));
}

// ---- chunked selective scan ----
// pass1: per (b, chunk, channel) compute diag product a[n] and local state h[n]
__global__ __launch_bounds__(512)
void k_scan1(const float* __restrict__ delta, const float* __restrict__ u,
             const float* __restrict__ dbc, const float* __restrict__ A_log,
             float* __restrict__ aprod, float* __restrict__ hloc) {
    int c = threadIdx.x;
    int b = blockIdx.x >> 4, g = blockIdx.x & 15;
    float An[DST], a[DST], h[DST];
    #pragma unroll
    for (int q = 0; q < 4; q++) {
        float4 v = *(const float4*)(A_log + c*DST + q*4);
        An[q*4+0] = -__expf(v.x); An[q*4+1] = -__expf(v.y);
        An[q*4+2] = -__expf(v.z); An[q*4+3] = -__expf(v.w);
    }
    #pragma unroll
    for (int n = 0; n < DST; n++) { a[n] = 1.f; h[n] = 0.f; }
    int r = b*SEQ + g*CHUNK;
    for (int t = 0; t < CHUNK; t++, r++) {
        float dl = __ldg(delta + r*DI + c);
        float uv = __ldg(u + r*DI + c);
        float du = dl * uv;
        const float4* Bp = (const float4*)(dbc + r*DBC_W + DTR);
        #pragma unroll
        for (int q = 0; q < 4; q++) {
            float4 Bv = __ldg(Bp + q);
            float e;
            e = __expf(dl*An[q*4+0]); a[q*4+0]*=e; h[q*4+0] = e*h[q*4+0] + du*Bv.x;
            e = __expf(dl*An[q*4+1]); a[q*4+1]*=e; h[q*4+1] = e*h[q*4+1] + du*Bv.y;
            e = __expf(dl*An[q*4+2]); a[q*4+2]*=e; h[q*4+2] = e*h[q*4+2] + du*Bv.z;
            e = __expf(dl*An[q*4+3]); a[q*4+3]*=e; h[q*4+3] = e*h[q*4+3] + du*Bv.w;
        }
    }
    int base = (blockIdx.x*DI + c)*DST;   // ((b*16+g)*512+c)*16
    #pragma unroll
    for (int q = 0; q < 4; q++) {
        *(float4*)(aprod + base + q*4) = make_float4(a[q*4],a[q*4+1],a[q*4+2],a[q*4+3]);
        *(float4*)(hloc  + base + q*4) = make_float4(h[q*4],h[q*4+1],h[q*4+2],h[q*4+3]);
    }
}

// sequential combine across 16 chunks per (b, c, n)
__global__ void k_comb(const float* __restrict__ aprod, const float* __restrict__ hloc,
                       float* __restrict__ hinit) {
    int t = blockIdx.x*blockDim.x + threadIdx.x;   // 65536 threads
    if (t >= BATCH*DI*DST) return;
    int b = t >> 13, cn = t & 8191;
    float run = 0.f;
    #pragma unroll
    for (int g = 0; g < NCHUNK; g++) {
        int idx = ((b*NCHUNK + g) << 13) + cn;
        hinit[idx] = run;
        run = aprod[idx]*run + hloc[idx];
    }
}

// pass2: replay chunk from correct initial state, emit (y + u*D)*silu(z)
__global__ __launch_bounds__(512)
void k_scan2(const float* __restrict__ delta, const float* __restrict__ u,
             const float* __restrict__ dbc, const float* __restrict__ A_log,
             const float* __restrict__ hinit, const float* __restrict__ xz,
             const float* __restrict__ Dsk, float* __restrict__ ya) {
    int c = threadIdx.x;
    int b = blockIdx.x >> 4, g = blockIdx.x & 15;
    float An[DST], h[DST];
    #pragma unroll
    for (int q = 0; q < 4; q++) {
        float4 v = *(const float4*)(A_log + c*DST + q*4);
        An[q*4+0] = -__expf(v.x); An[q*4+1] = -__expf(v.y);
        An[q*4+2] = -__expf(v.z); An[q*4+3] = -__expf(v.w);
    }
    int base = (blockIdx.x*DI + c)*DST;
    #pragma unroll
    for (int q = 0; q < 4; q++) {
        float4 v = *(const float4*)(hinit + base + q*4);
        h[q*4+0]=v.x; h[q*4+1]=v.y; h[q*4+2]=v.z; h[q*4+3]=v.w;
    }
    float Dc = Dsk[c];
    int r = b*SEQ + g*CHUNK;
    for (int t = 0; t < CHUNK; t++, r++) {
        float dl = __ldg(delta + r*DI + c);
        float uv = __ldg(u + r*DI + c);
        float du = dl * uv;
        const float4* Bp = (const float4*)(dbc + r*DBC_W + DTR);
        const float4* Cp = (const float4*)(dbc + r*DBC_W + DTR + DST);
        float y = 0.f;
        #pragma unroll
        for (int q = 0; q < 4; q++) {
            float4 Bv = __ldg(Bp + q);
            float4 Cv = __ldg(Cp + q);
            float e;
            e = __expf(dl*An[q*4+0]); h[q*4+0] = e*h[q*4+0] + du*Bv.x; y += h[q*4+0]*Cv.x;
            e = __expf(dl*An[q*4+1]); h[q*4+1] = e*h[q*4+1] + du*Bv.y; y += h[q*4+1]*Cv.y;
            e = __expf(dl*An[q*4+2]); h[q*4+2] = e*h[q*4+2] + du*Bv.z; y += h[q*4+2]*Cv.z;
            e = __expf(dl*An[q*4+3]); h[q*4+3] = e*h[q*4+3] + du*Bv.w; y += h[q*4+3]*Cv.w;
        }
        float z = xz[r*2*DI + DI + c];
        ya[r*DI + c] = (y + uv*Dc) * silu(z);
    }
}

// out[r] = dot(h[r,:], w_head) + b_head.  8 warps/block, warp per row.
__global__ void k_head(const float* __restrict__ h, const float* __restrict__ wh,
                       const float* __restrict__ bh, float* __restrict__ out) {
    int r = blockIdx.x*8 + (threadIdx.x >> 5);
    int lane = threadIdx.x & 31;
    float s = 0.f;
    #pragma unroll
    for (int j = lane; j < DM; j += 32) s += h[r*DM + j] * wh[j];
    #pragma unroll
    for (int off = 16; off > 0; off >>= 1) s += __shfl_xor_sync(0xffffffffu, s, off);
    if (lane == 0) out[r] = s + bh[0];
}

// ---------------- launch ----------------
extern "C" void kernel_launch(void* const* d_in, const int* in_sizes, int n_in,
                              void* d_out, int out_size) {
    const float* x        = (const float*)d_in[0];
    const float* w_in     = (const float*)d_in[1];
    const float* b_in     = (const float*)d_in[2];
    const float* norm_w   = (const float*)d_in[3];
    const float* in_proj  = (const float*)d_in[4];
    const float* conv_w   = (const float*)d_in[5];
    const float* conv_b   = (const float*)d_in[6];
    const float* x_proj   = (const float*)d_in[7];
    const float* dt_w     = (const float*)d_in[8];
    const float* dt_b     = (const float*)d_in[9];
    const float* A_log    = (const float*)d_in[10];
    const float* D_skip   = (const float*)d_in[11];
    const float* out_proj = (const float*)d_in[12];
    const float* w_head   = (const float*)d_in[13];
    const float* b_head   = (const float*)d_in[14];

    float *h, *xn, *xz, *u, *dbc, *delta, *ya, *ap, *hl, *hi;
    cudaGetSymbolAddress((void**)&h,    g_h);
    cudaGetSymbolAddress((void**)&xn,   g_xn);
    cudaGetSymbolAddress((void**)&xz,   g_xz);
    cudaGetSymbolAddress((void**)&u,    g_u);
    cudaGetSymbolAddress((void**)&dbc,  g_dbc);
    cudaGetSymbolAddress((void**)&delta,g_delta);
    cudaGetSymbolAddress((void**)&ya,   g_ya);
    cudaGetSymbolAddress((void**)&ap,   g_ap);
    cudaGetSymbolAddress((void**)&hl,   g_hl);
    cudaGetSymbolAddress((void**)&hi,   g_hi);

    k_embed<<<(BS_TOT*DM)/256, 256>>>(x, w_in, b_in, h);

    for (int i = 0; i < NLAYER; i++) {
        k_rmsnorm<<<BS_TOT, 256>>>(h, norm_w + i*DM, xn);
        // xz = xn @ in_proj^T : M=16384, N=1024, K=256
        sgemm_nt<false><<<dim3(BS_TOT/128, (2*DI)/64), 256>>>(
            xn, in_proj + i*2*DI*DM, xz, DM, DM, DM, 2*DI);
        k_conv<<<(BS_TOT*DI)/256, 256>>>(xz, conv_w + i*DI*4, conv_b + i*DI, u);
        k_xproj<<<BS_TOT/4, dim3(48,4)>>>(u, x_proj + i*DBC_W*DI, dbc);
        k_dt<<<(BS_TOT*DI)/256, 256>>>(dbc, dt_w + i*DI*DTR, dt_b + i*DI, delta);
        k_scan1<<<BATCH*NCHUNK, DI>>>(delta, u, dbc, A_log + i*DI*DST, ap, hl);
        k_comb<<<(BATCH*DI*DST)/256, 256>>>(ap, hl, hi);
        k_scan2<<<BATCH*NCHUNK, DI>>>(delta, u, dbc, A_log + i*DI*DST, hi, xz,
                                      D_skip + i*DI, ya);
        // h += ya @ out_proj^T : M=16384, N=256, K=512
        sgemm_nt<true><<<dim3(BS_TOT/128, DM/64), 256>>>(
            ya, out_proj + i*DM*DI, h, DI, DI, DI, DM);
    }

    k_head<<<BS_TOT/8, 256>>>(h, w_head, b_head, (float*)d_out);
}

// round 2
// speedup vs baseline: 1.3117x; 1.3117x over previous
#include <cuda_runtime.h>
#include <cuda_bf16.h>

// ---------------- problem constants ----------------
#define BATCH   8
#define SEQ     2048
#define BS_TOT  (BATCH*SEQ)      // 16384 rows
#define DM      256              // d_model
#define DI      512              // d_inner
#define DST     16               // d_state
#define DTR     16               // dt_rank
#define NLAYER  4
#define DBC_W   48               // dt_rank + 2*d_state
#define NCHUNK  64
#define CHUNK   32               // SEQ / NCHUNK

// ---------------- scratch (device globals; no allocation allowed) ----------------
__device__ float g_h    [BS_TOT*DM];
__device__ float g_xn   [BS_TOT*DM];
__device__ float g_xz   [BS_TOT*2*DI];
__device__ float g_u    [BS_TOT*DI];
__device__ float g_dbc  [BS_TOT*DBC_W];
__device__ float g_delta[BS_TOT*DI];
__device__ float g_ya   [BS_TOT*DI];
__device__ float g_ap   [BATCH*NCHUNK*DI*DST];
__device__ float g_hl   [BATCH*NCHUNK*DI*DST];
__device__ float g_hi   [BATCH*NCHUNK*DI*DST];

// ---------------- helpers ----------------
__device__ __forceinline__ float silu(float x) { return x / (1.f + __expf(-x)); }

__device__ __forceinline__ float to_tf32(float x) {
    float y;
    asm("cvt.rna.tf32.f32 %0, %1;" : "=f"(y) : "f"(x));
    return y;
}

__device__ __forceinline__ void mma_tf32(float d[4], const unsigned a[4], const unsigned b[2]) {
    asm volatile(
        "mma.sync.aligned.m16n8k8.row.col.f32.tf32.tf32.f32 "
        "{%0,%1,%2,%3},{%4,%5,%6,%7},{%8,%9},{%0,%1,%2,%3};"
        : "+f"(d[0]), "+f"(d[1]), "+f"(d[2]), "+f"(d[3])
        : "r"(a[0]), "r"(a[1]), "r"(a[2]), "r"(a[3]), "r"(b[0]), "r"(b[1]));
}

// ---------------- kernels ----------------

__global__ void k_embed(const float* __restrict__ x, const float* __restrict__ w_in,
                        const float* __restrict__ b_in, float* __restrict__ h) {
    int i = blockIdx.x*blockDim.x + threadIdx.x;
    if (i >= BS_TOT*DM) return;
    int r = i >> 8, d = i & (DM-1);
    h[i] = x[2*r]*w_in[2*d] + x[2*r+1]*w_in[2*d+1] + b_in[d];
}

__global__ void k_rmsnorm(const float* __restrict__ h, const float* __restrict__ w,
                          float* __restrict__ xn) {
    int r = blockIdx.x, d = threadIdx.x;
    float v = h[r*DM + d];
    float s = v*v;
    #pragma unroll
    for (int off = 16; off > 0; off >>= 1) s += __shfl_xor_sync(0xffffffffu, s, off);
    __shared__ float red[8];
    __shared__ float scale;
    int lane = d & 31, warp = d >> 5;
    if (lane == 0) red[warp] = s;
    __syncthreads();
    if (d == 0) {
        float t = 0.f;
        #pragma unroll
        for (int i = 0; i < 8; i++) t += red[i];
        scale = rsqrtf(t * (1.0f/DM) + 1e-5f);
    }
    __syncthreads();
    xn[r*DM + d] = v * scale * w[d];
}

// ---- tf32 tensor-core GEMM: C[M,N] = A[M,K] @ B[N,K]^T (row-major, K contiguous)
// block tile 128x64x16, 256 threads, 8 warps in 4(m) x 2(n), warp tile 32x32.
#define BM 128
#define BN 64
#define BK 16
#define BKP (BK+4)   // pad -> conflict-free fragment LDS (verified mod-32 distinct)

template<bool ACC>
__global__ __launch_bounds__(256)
void gemm_tc(const float* __restrict__ A, const float* __restrict__ B,
             float* __restrict__ C, int K, int lda, int ldb, int ldc) {
    __shared__ float As[2][BM][BKP];
    __shared__ float Bs[2][BN][BKP];

    const int m0 = blockIdx.x * BM, n0 = blockIdx.y * BN;
    const int tid  = threadIdx.x;
    const int lane = tid & 31, warp = tid >> 5;
    const int wm = (warp & 3) * 32, wn = (warp >> 2) * 32;
    const int lr = lane >> 2, lc = lane & 3;

    // global-load assignments
    // A: 128x16 = 512 float4, 2 per thread
    const int ar0 = tid >> 2, ac = (tid & 3) * 4;         // rows tid/4 and tid/4+64
    // B: 64x16 = 256 float4, 1 per thread
    const int br = tid >> 2, bc = (tid & 3) * 4;

    float4 pa0, pa1, pb;
    const int nk = K / BK;

    // prologue: load tile 0
    pa0 = *(const float4*)(A + (m0+ar0   )*lda + ac);
    pa1 = *(const float4*)(A + (m0+ar0+64)*lda + ac);
    pb  = *(const float4*)(B + (n0+br    )*ldb + bc);
    {
        float* s0 = &As[0][ar0   ][ac];
        float* s1 = &As[0][ar0+64][ac];
        float* s2 = &Bs[0][br    ][bc];
        s0[0]=to_tf32(pa0.x); s0[1]=to_tf32(pa0.y); s0[2]=to_tf32(pa0.z); s0[3]=to_tf32(pa0.w);
        s1[0]=to_tf32(pa1.x); s1[1]=to_tf32(pa1.y); s1[2]=to_tf32(pa1.z); s1[3]=to_tf32(pa1.w);
        s2[0]=to_tf32(pb.x);  s2[1]=to_tf32(pb.y);  s2[2]=to_tf32(pb.z);  s2[3]=to_tf32(pb.w);
    }
    __syncthreads();

    float acc[2][4][4];
    #pragma unroll
    for (int mi = 0; mi < 2; mi++)
        #pragma unroll
        for (int ni = 0; ni < 4; ni++)
            #pragma unroll
            for (int q = 0; q < 4; q++) acc[mi][ni][q] = 0.f;

    for (int it = 0; it < nk; it++) {
        const int cur = it & 1;
        if (it + 1 < nk) {
            const int k0 = (it+1) * BK;
            pa0 = *(const float4*)(A + (m0+ar0   )*lda + k0 + ac);
            pa1 = *(const float4*)(A + (m0+ar0+64)*lda + k0 + ac);
            pb  = *(const float4*)(B + (n0+br    )*ldb + k0 + bc);
        }
        #pragma unroll
        for (int kk = 0; kk < 2; kk++) {
            unsigned a[2][4], b[4][2];
            #pragma unroll
            for (int mi = 0; mi < 2; mi++) {
                int r = wm + mi*16;
                a[mi][0] = __float_as_uint(As[cur][r+lr  ][kk*8+lc  ]);
                a[mi][1] = __float_as_uint(As[cur][r+lr+8][kk*8+lc  ]);
                a[mi][2] = __float_as_uint(As[cur][r+lr  ][kk*8+lc+4]);
                a[mi][3] = __float_as_uint(As[cur][r+lr+8][kk*8+lc+4]);
            }
            #pragma unroll
            for (int ni = 0; ni < 4; ni++) {
                int n = wn + ni*8;
                b[ni][0] = __float_as_uint(Bs[cur][n+lr][kk*8+lc  ]);
                b[ni][1] = __float_as_uint(Bs[cur][n+lr][kk*8+lc+4]);
            }
            #pragma unroll
            for (int mi = 0; mi < 2; mi++)
                #pragma unroll
                for (int ni = 0; ni < 4; ni++)
                    mma_tf32(acc[mi][ni], a[mi], b[ni]);
        }
        if (it + 1 < nk) {
            const int nxt = (it+1) & 1;
            float* s0 = &As[nxt][ar0   ][ac];
            float* s1 = &As[nxt][ar0+64][ac];
            float* s2 = &Bs[nxt][br    ][bc];
            s0[0]=to_tf32(pa0.x); s0[1]=to_tf32(pa0.y); s0[2]=to_tf32(pa0.z); s0[3]=to_tf32(pa0.w);
            s1[0]=to_tf32(pa1.x); s1[1]=to_tf32(pa1.y); s1[2]=to_tf32(pa1.z); s1[3]=to_tf32(pa1.w);
            s2[0]=to_tf32(pb.x);  s2[1]=to_tf32(pb.y);  s2[2]=to_tf32(pb.z);  s2[3]=to_tf32(pb.w);
            __syncthreads();
        }
    }

    // epilogue
    #pragma unroll
    for (int mi = 0; mi < 2; mi++) {
        #pragma unroll
        for (int ni = 0; ni < 4; ni++) {
            int row = m0 + wm + mi*16 + lr;
            int col = n0 + wn + ni*8 + 2*lc;
            float2 v0 = make_float2(acc[mi][ni][0], acc[mi][ni][1]);
            float2 v1 = make_float2(acc[mi][ni][2], acc[mi][ni][3]);
            float* p0 = C + row*ldc + col;
            float* p1 = C + (row+8)*ldc + col;
            if (ACC) {
                float2 o0 = *(const float2*)p0, o1 = *(const float2*)p1;
                v0.x += o0.x; v0.y += o0.y; v1.x += o1.x; v1.y += o1.y;
            }
            *(float2*)p0 = v0;
            *(float2*)p1 = v1;
        }
    }
}

__global__ void k_conv(const float* __restrict__ xz, const float* __restrict__ cw,
                       const float* __restrict__ cb, float* __restrict__ u) {
    int i = blockIdx.x*blockDim.x + threadIdx.x;
    if (i >= BS_TOT*DI) return;
    int c = i & (DI-1), r = i >> 9, s = r & (SEQ-1);
    float4 w = *(const float4*)(cw + c*4);
    float acc = cb[c];
    if (s >= 3) acc += w.x * xz[(r-3)*2*DI + c];
    if (s >= 2) acc += w.y * xz[(r-2)*2*DI + c];
    if (s >= 1) acc += w.z * xz[(r-1)*2*DI + c];
    acc += w.w * xz[r*2*DI + c];
    u[i] = silu(acc);
}

__global__ void k_xproj(const float* __restrict__ u, const float* __restrict__ w,
                        float* __restrict__ dbc) {
    __shared__ float su[4*DI];
    int r0 = blockIdx.x * 4;
    int tid = threadIdx.y*48 + threadIdx.x;
    for (int i = tid; i < 4*DI; i += 192) su[i] = u[r0*DI + i];
    __syncthreads();
    int col = threadIdx.x, ry = threadIdx.y;
    const float4* w4 = (const float4*)(w + col*DI);
    const float4* u4 = (const float4*)(su + ry*DI);
    float acc = 0.f;
    #pragma unroll 8
    for (int k = 0; k < DI/4; k++) {
        float4 a = u4[k], b = __ldg(w4 + k);
        acc += a.x*b.x + a.y*b.y + a.z*b.z + a.w*b.w;
    }
    dbc[(r0+ry)*DBC_W + col] = acc;
}

__global__ void k_dt(const float* __restrict__ dbc, const float* __restrict__ dtw,
                     const float* __restrict__ dtb, float* __restrict__ delta) {
    int i = blockIdx.x*blockDim.x + threadIdx.x;
    if (i >= BS_TOT*DI) return;
    int c = i & (DI-1), r = i >> 9;
    const float4* d4 = (const float4*)(dbc + r*DBC_W);
    const float4* w4 = (const float4*)(dtw + c*DTR);
    float acc = dtb[c];
    #pragma unroll
    for (int q = 0; q < 4; q++) {
        float4 a = __ldg(d4 + q), b = __ldg(w4 + q);
        acc += a.x*b.x + a.y*b.y + a.z*b.z + a.w*b.w;
    }
    delta[i] = (acc > 20.f) ? acc : log1pf(__expf(acc));
}

// ---- chunked selective scan ----
__global__ __launch_bounds__(512)
void k_scan1(const float* __restrict__ delta, const float* __restrict__ u,
             const float* __restrict__ dbc, const float* __restrict__ A_log,
             float* __restrict__ aprod, float* __restrict__ hloc) {
    int c = threadIdx.x;
    int b = blockIdx.x >> 6, g = blockIdx.x & (NCHUNK-1);
    float An[DST], a[DST], h[DST];
    #pragma unroll
    for (int q = 0; q < 4; q++) {
        float4 v = *(const float4*)(A_log + c*DST + q*4);
        An[q*4+0] = -__expf(v.x); An[q*4+1] = -__expf(v.y);
        An[q*4+2] = -__expf(v.z); An[q*4+3] = -__expf(v.w);
    }
    #pragma unroll
    for (int n = 0; n < DST; n++) { a[n] = 1.f; h[n] = 0.f; }
    int r = b*SEQ + g*CHUNK;
    for (int t = 0; t < CHUNK; t++, r++) {
        float dl = __ldg(delta + r*DI + c);
        float uv = __ldg(u + r*DI + c);
        float du = dl * uv;
        const float4* Bp = (const float4*)(dbc + r*DBC_W + DTR);
        #pragma unroll
        for (int q = 0; q < 4; q++) {
            float4 Bv = __ldg(Bp + q);
            float e;
            e = __expf(dl*An[q*4+0]); a[q*4+0]*=e; h[q*4+0] = e*h[q*4+0] + du*Bv.x;
            e = __expf(dl*An[q*4+1]); a[q*4+1]*=e; h[q*4+1] = e*h[q*4+1] + du*Bv.y;
            e = __expf(dl*An[q*4+2]); a[q*4+2]*=e; h[q*4+2] = e*h[q*4+2] + du*Bv.z;
            e = __expf(dl*An[q*4+3]); a[q*4+3]*=e; h[q*4+3] = e*h[q*4+3] + du*Bv.w;
        }
    }
    int base = (blockIdx.x*DI + c)*DST;
    #pragma unroll
    for (int q = 0; q < 4; q++) {
        *(float4*)(aprod + base + q*4) = make_float4(a[q*4],a[q*4+1],a[q*4+2],a[q*4+3]);
        *(float4*)(hloc  + base + q*4) = make_float4(h[q*4],h[q*4+1],h[q*4+2],h[q*4+3]);
    }
}

__global__ void k_comb(const float* __restrict__ aprod, const float* __restrict__ hloc,
                       float* __restrict__ hinit) {
    int t = blockIdx.x*blockDim.x + threadIdx.x;
    if (t >= BATCH*DI*DST) return;
    int b = t >> 13, cn = t & 8191;
    float run = 0.f;
    #pragma unroll
    for (int g = 0; g < NCHUNK; g++) {
        int idx = ((b*NCHUNK + g) << 13) + cn;
        hinit[idx] = run;
        run = aprod[idx]*run + hloc[idx];
    }
}

__global__ __launch_bounds__(512)
void k_scan2(const float* __restrict__ delta, const float* __restrict__ u,
             const float* __restrict__ dbc, const float* __restrict__ A_log,
             const float* __restrict__ hinit, const float* __restrict__ xz,
             const float* __restrict__ Dsk, float* __restrict__ ya) {
    int c = threadIdx.x;
    int b = blockIdx.x >> 6, g = blockIdx.x & (NCHUNK-1);
    float An[DST], h[DST];
    #pragma unroll
    for (int q = 0; q < 4; q++) {
        float4 v = *(const float4*)(A_log + c*DST + q*4);
        An[q*4+0] = -__expf(v.x); An[q*4+1] = -__expf(v.y);
        An[q*4+2] = -__expf(v.z); An[q*4+3] = -__expf(v.w);
    }
    int base = (blockIdx.x*DI + c)*DST;
    #pragma unroll
    for (int q = 0; q < 4; q++) {
        float4 v = *(const float4*)(hinit + base + q*4);
        h[q*4+0]=v.x; h[q*4+1]=v.y; h[q*4+2]=v.z; h[q*4+3]=v.w;
    }
    float Dc = Dsk[c];
    int r = b*SEQ + g*CHUNK;
    for (int t = 0; t < CHUNK; t++, r++) {
        float dl = __ldg(delta + r*DI + c);
        float uv = __ldg(u + r*DI + c);
        float du = dl * uv;
        const float4* Bp = (const float4*)(dbc + r*DBC_W + DTR);
        const float4* Cp = (const float4*)(dbc + r*DBC_W + DTR + DST);
        float y = 0.f;
        #pragma unroll
        for (int q = 0; q < 4; q++) {
            float4 Bv = __ldg(Bp + q);
            float4 Cv = __ldg(Cp + q);
            float e;
            e = __expf(dl*An[q*4+0]); h[q*4+0] = e*h[q*4+0] + du*Bv.x; y += h[q*4+0]*Cv.x;
            e = __expf(dl*An[q*4+1]); h[q*4+1] = e*h[q*4+1] + du*Bv.y; y += h[q*4+1]*Cv.y;
            e = __expf(dl*An[q*4+2]); h[q*4+2] = e*h[q*4+2] + du*Bv.z; y += h[q*4+2]*Cv.z;
            e = __expf(dl*An[q*4+3]); h[q*4+3] = e*h[q*4+3] + du*Bv.w; y += h[q*4+3]*Cv.w;
        }
        float z = xz[r*2*DI + DI + c];
        ya[r*DI + c] = (y + uv*Dc) * silu(z);
    }
}

__global__ void k_head(const float* __restrict__ h, const float* __restrict__ wh,
                       const float* __restrict__ bh, float* __restrict__ out) {
    int r = blockIdx.x*8 + (threadIdx.x >> 5);
    int lane = threadIdx.x & 31;
    float s = 0.f;
    #pragma unroll
    for (int j = lane; j < DM; j += 32) s += h[r*DM + j] * wh[j];
    #pragma unroll
    for (int off = 16; off > 0; off >>= 1) s += __shfl_xor_sync(0xffffffffu, s, off);
    if (lane == 0) out[r] = s + bh[0];
}

// ---------------- launch ----------------
extern "C" void kernel_launch(void* const* d_in, const int* in_sizes, int n_in,
                              void* d_out, int out_size) {
    const float* x        = (const float*)d_in[0];
    const float* w_in     = (const float*)d_in[1];
    const float* b_in     = (const float*)d_in[2];
    const float* norm_w   = (const float*)d_in[3];
    const float* in_proj  = (const float*)d_in[4];
    const float* conv_w   = (const float*)d_in[5];
    const float* conv_b   = (const float*)d_in[6];
    const float* x_proj   = (const float*)d_in[7];
    const float* dt_w     = (const float*)d_in[8];
    const float* dt_b     = (const float*)d_in[9];
    const float* A_log    = (const float*)d_in[10];
    const float* D_skip   = (const float*)d_in[11];
    const float* out_proj = (const float*)d_in[12];
    const float* w_head   = (const float*)d_in[13];
    const float* b_head   = (const float*)d_in[14];

    float *h, *xn, *xz, *u, *dbc, *delta, *ya, *ap, *hl, *hi;
    cudaGetSymbolAddress((void**)&h,    g_h);
    cudaGetSymbolAddress((void**)&xn,   g_xn);
    cudaGetSymbolAddress((void**)&xz,   g_xz);
    cudaGetSymbolAddress((void**)&u,    g_u);
    cudaGetSymbolAddress((void**)&dbc,  g_dbc);
    cudaGetSymbolAddress((void**)&delta,g_delta);
    cudaGetSymbolAddress((void**)&ya,   g_ya);
    cudaGetSymbolAddress((void**)&ap,   g_ap);
    cudaGetSymbolAddress((void**)&hl,   g_hl);
    cudaGetSymbolAddress((void**)&hi,   g_hi);

    k_embed<<<(BS_TOT*DM)/256, 256>>>(x, w_in, b_in, h);

    for (int i = 0; i < NLAYER; i++) {
        k_rmsnorm<<<BS_TOT, 256>>>(h, norm_w + i*DM, xn);
        // xz = xn @ in_proj^T : M=16384, N=1024, K=256
        gemm_tc<false><<<dim3(BS_TOT/BM, (2*DI)/BN), 256>>>(
            xn, in_proj + i*2*DI*DM, xz, DM, DM, DM, 2*DI);
        k_conv<<<(BS_TOT*DI)/256, 256>>>(xz, conv_w + i*DI*4, conv_b + i*DI, u);
        k_xproj<<<BS_TOT/4, dim3(48,4)>>>(u, x_proj + i*DBC_W*DI, dbc);
        k_dt<<<(BS_TOT*DI)/256, 256>>>(dbc, dt_w + i*DI*DTR, dt_b + i*DI, delta);
        k_scan1<<<BATCH*NCHUNK, DI>>>(delta, u, dbc, A_log + i*DI*DST, ap, hl);
        k_comb<<<(BATCH*DI*DST)/256, 256>>>(ap, hl, hi);
        k_scan2<<<BATCH*NCHUNK, DI>>>(delta, u, dbc, A_log + i*DI*DST, hi, xz,
                                      D_skip + i*DI, ya);
        // h += ya @ out_proj^T : M=16384, N=256, K=512
        gemm_tc<true><<<dim3(BS_TOT/BM, DM/BN), 256>>>(
            ya, out_proj + i*DM*DI, h, DI, DI, DI, DM);
    }

    k_head<<<BS_TOT/8, 256>>>(h, w_head, b_head, (float*)d_out);
}